// round 10
// baseline (speedup 1.0000x reference)
#include <cuda_runtime.h>
#include <cuda_bf16.h>
#include <cstdint>
#include <cstddef>

// Problem constants
#define NB  4
#define CC  256
#define HWD 4096

// ---------------------------------------------------------------------------
// Static device scratch (no allocation allowed)
// ---------------------------------------------------------------------------
__device__ __nv_bfloat16 g_thetaT[(size_t)NB * HWD * CC]; // 8 MB, [n][p][c]
__device__ __nv_bfloat16 g_phiT[(size_t)NB * HWD * CC];   // 8 MB, [n][q][c]
__device__ __nv_bfloat16 g_xbf[(size_t)NB * CC * HWD];    // 8 MB, [n][c][q]
__device__ __nv_bfloat16 g_expS[(size_t)NB * HWD * HWD];  // 128 MB, [n][p][q]
__device__ float g_rowsum[NB * HWD];                      // 64 KB
__device__ float g_f[(size_t)NB * CC * HWD];              // 16 MB

// ---------------------------------------------------------------------------
// Helpers (all sm_80/75-baseline PTX — no 'a'-suffix features)
// ---------------------------------------------------------------------------
__device__ __forceinline__ uint32_t smem_u32(const void* p) {
    uint32_t a;
    asm("{ .reg .u64 t; cvta.to.shared.u64 t, %1; cvt.u32.u64 %0, t; }"
        : "=r"(a) : "l"(p));
    return a;
}

__device__ __forceinline__ uint32_t f22bf(float x, float y) {
    __nv_bfloat162 h = __floats2bfloat162_rn(x, y);   // low = x
    return *reinterpret_cast<uint32_t*>(&h);
}

__device__ __forceinline__ void ldsm_x4(uint32_t& r0, uint32_t& r1,
                                        uint32_t& r2, uint32_t& r3,
                                        uint32_t addr)
{
    asm volatile("ldmatrix.sync.aligned.m8n8.x4.shared.b16 {%0,%1,%2,%3}, [%4];"
                 : "=r"(r0), "=r"(r1), "=r"(r2), "=r"(r3) : "r"(addr));
}

__device__ __forceinline__ void mma_bf16(float d[4],
                                         uint32_t a0, uint32_t a1,
                                         uint32_t a2, uint32_t a3,
                                         uint32_t b0, uint32_t b1)
{
    asm volatile(
        "mma.sync.aligned.m16n8k16.row.col.f32.bf16.bf16.f32 "
        "{%0,%1,%2,%3}, {%4,%5,%6,%7}, {%8,%9}, {%0,%1,%2,%3};\n"
        : "+f"(d[0]), "+f"(d[1]), "+f"(d[2]), "+f"(d[3])
        : "r"(a0), "r"(a1), "r"(a2), "r"(a3), "r"(b0), "r"(b1));
}

#define KC  64   // k-elements per smem chunk (bf16)
#define SMH 72   // smem row stride in halfs (144 B) -> LDSM conflict-free

// ---------------------------------------------------------------------------
// Init: zero rowsum; convert x -> bf16 copy
// ---------------------------------------------------------------------------
__global__ void zero_rowsum_kernel(float* __restrict__ rowsum)
{
    rowsum[blockIdx.x * 256 + threadIdx.x] = 0.f;
}

__global__ void cvt_x_kernel(const float* __restrict__ x,
                             __nv_bfloat16* __restrict__ xbf)
{
    size_t i = ((size_t)blockIdx.x * 256 + threadIdx.x) * 8;
    float4 v0 = *(const float4*)(x + i);
    float4 v1 = *(const float4*)(x + i + 4);
    uint4 o;
    o.x = f22bf(v0.x, v0.y);
    o.y = f22bf(v0.z, v0.w);
    o.z = f22bf(v1.x, v1.y);
    o.w = f22bf(v1.z, v1.w);
    *(uint4*)(xbf + i) = o;
}

// ---------------------------------------------------------------------------
// Generic bf16 tile loader: [128 rows x 64 halfs] -> swizzle-free padded smem.
// src row stride rstride halfs; 8 uint4 chunks per row; 4 chunks per thread.
// ---------------------------------------------------------------------------
__device__ __forceinline__ void load_bf_tile(const __nv_bfloat16* __restrict__ src,
                                             size_t rstride, uint16_t* dst, int t)
{
#pragma unroll
    for (int i = 0; i < 4; ++i) {
        int v  = t + i * 256;
        int r  = v >> 3;
        int ch = (v & 7) << 3;
        *(uint4*)(dst + r * SMH + ch) = *(const uint4*)(src + (size_t)r * rstride + ch);
    }
}

// ---------------------------------------------------------------------------
// Scores (bf16 MMA): expS[n,p,q] = bf16( exp( (thT[p,:]·phT[q,:]) / 16 ) )
// Block tile 128(p) x 128(q), K = C = 256 in chunks of 64 (4 k16 steps).
// 8 warps: wm 0..3 (32 p-rows), wn 0..1 (64 q-cols). Rowsums from the
// ROUNDED bf16 values (exact softmax normalization), quad-shfl + atomicAdd.
// ---------------------------------------------------------------------------
__global__ __launch_bounds__(256, 2)
void scores_mma_kernel(const __nv_bfloat16* __restrict__ thT,
                       const __nv_bfloat16* __restrict__ phT,
                       __nv_bfloat16* __restrict__ expS,
                       float* __restrict__ rowsum)
{
    __shared__ __align__(16) uint16_t As[128 * SMH];
    __shared__ __align__(16) uint16_t Bs[128 * SMH];

    const int t    = threadIdx.x;
    const int lane = t & 31;
    const int wid  = t >> 5;
    const int g    = lane >> 2;
    const int tq   = lane & 3;
    const int wm   = wid & 3;
    const int wn   = wid >> 2;

    const int q0 = blockIdx.x * 128;
    const int p0 = blockIdx.y * 128;
    const int n  = blockIdx.z;

    const __nv_bfloat16* Ag = thT + ((size_t)n * HWD + p0) * CC;
    const __nv_bfloat16* Bg = phT + ((size_t)n * HWD + q0) * CC;

    const uint32_t sA = smem_u32(As), sB = smem_u32(Bs);
    uint32_t a_addr[2], b_addr[4];
#pragma unroll
    for (int mt = 0; mt < 2; ++mt) {
        int rowA = wm * 32 + mt * 16 + (lane & 15);
        int col  = (lane >> 4) * 8;
        a_addr[mt] = sA + (uint32_t)(rowA * SMH + col) * 2;
    }
#pragma unroll
    for (int ntp = 0; ntp < 4; ++ntp) {
        int rowB = wn * 64 + ntp * 16 + ((lane >> 4) & 1) * 8 + (lane & 7);
        int col  = ((lane >> 3) & 1) * 8;
        b_addr[ntp] = sB + (uint32_t)(rowB * SMH + col) * 2;
    }

    float d[2][8][4];
#pragma unroll
    for (int mt = 0; mt < 2; ++mt)
#pragma unroll
        for (int nt = 0; nt < 8; ++nt)
#pragma unroll
            for (int j = 0; j < 4; ++j) d[mt][nt][j] = 0.f;

    for (int kt = 0; kt < CC; kt += KC) {
        load_bf_tile(Ag + kt, CC, As, t);
        load_bf_tile(Bg + kt, CC, Bs, t);
        __syncthreads();
#pragma unroll
        for (int kh = 0; kh < 4; ++kh) {
            const uint32_t off = kh * 32;          // 16 halfs = 32 B
            uint32_t a[2][4], b[4][4];
#pragma unroll
            for (int mt = 0; mt < 2; ++mt)
                ldsm_x4(a[mt][0], a[mt][1], a[mt][2], a[mt][3], a_addr[mt] + off);
#pragma unroll
            for (int ntp = 0; ntp < 4; ++ntp)
                ldsm_x4(b[ntp][0], b[ntp][1], b[ntp][2], b[ntp][3], b_addr[ntp] + off);
#pragma unroll
            for (int mt = 0; mt < 2; ++mt)
#pragma unroll
                for (int nt = 0; nt < 8; ++nt)
                    mma_bf16(d[mt][nt], a[mt][0], a[mt][1], a[mt][2], a[mt][3],
                             b[nt >> 1][(nt & 1) * 2], b[nt >> 1][(nt & 1) * 2 + 1]);
        }
        __syncthreads();
    }

    // Epilogue: exp -> bf16 round -> store; row sums of ROUNDED values
    __nv_bfloat16* Sn = expS + (size_t)n * HWD * HWD;
    float rs[2][2] = {{0.f, 0.f}, {0.f, 0.f}};
#pragma unroll
    for (int mt = 0; mt < 2; ++mt) {
        const int row = p0 + wm * 32 + mt * 16 + g;
#pragma unroll
        for (int nt = 0; nt < 8; ++nt) {
            const int col = q0 + wn * 64 + nt * 8 + 2 * tq;
            float e0 = __expf(d[mt][nt][0] * 0.0625f);
            float e1 = __expf(d[mt][nt][1] * 0.0625f);
            float e2 = __expf(d[mt][nt][2] * 0.0625f);
            float e3 = __expf(d[mt][nt][3] * 0.0625f);
            __nv_bfloat162 lo = __floats2bfloat162_rn(e0, e1);
            __nv_bfloat162 hi = __floats2bfloat162_rn(e2, e3);
            *(uint32_t*)(Sn + (size_t)row * HWD + col)       = *(uint32_t*)&lo;
            *(uint32_t*)(Sn + (size_t)(row + 8) * HWD + col) = *(uint32_t*)&hi;
            rs[mt][0] += __bfloat162float(lo.x) + __bfloat162float(lo.y);
            rs[mt][1] += __bfloat162float(hi.x) + __bfloat162float(hi.y);
        }
    }
#pragma unroll
    for (int mt = 0; mt < 2; ++mt)
#pragma unroll
        for (int hh = 0; hh < 2; ++hh) {
            float v = rs[mt][hh];
            v += __shfl_xor_sync(0xFFFFFFFF, v, 1);
            v += __shfl_xor_sync(0xFFFFFFFF, v, 2);
            if (tq == 0)
                atomicAdd(&rowsum[n * HWD + p0 + wm * 32 + mt * 16 + g + hh * 8], v);
        }
}

// ---------------------------------------------------------------------------
// PV (bf16 MMA): f[n,c,p] = (sum_q xbf[c,q]*expS[p,q]) / rowsum[p]
// Block tile 128(c) x 128(p), K = HW = 4096 in chunks of 64.
// ---------------------------------------------------------------------------
__global__ __launch_bounds__(256, 2)
void pv_mma_kernel(const __nv_bfloat16* __restrict__ xbf,
                   const __nv_bfloat16* __restrict__ expS,
                   const float* __restrict__ rowsum,
                   float* __restrict__ f)
{
    __shared__ __align__(16) uint16_t As[128 * SMH];
    __shared__ __align__(16) uint16_t Bs[128 * SMH];
    __shared__ float rinv[128];

    const int t    = threadIdx.x;
    const int lane = t & 31;
    const int wid  = t >> 5;
    const int g    = lane >> 2;
    const int tq   = lane & 3;
    const int wm   = wid & 3;
    const int wn   = wid >> 2;

    const int p0 = blockIdx.x * 128;
    const int c0 = blockIdx.y * 128;
    const int n  = blockIdx.z;

    if (t < 128) rinv[t] = 1.0f / rowsum[n * HWD + p0 + t];

    const __nv_bfloat16* Ag = xbf  + (size_t)n * CC * HWD + (size_t)c0 * HWD;
    const __nv_bfloat16* Bg = expS + (size_t)n * HWD * HWD + (size_t)p0 * HWD;

    const uint32_t sA = smem_u32(As), sB = smem_u32(Bs);
    uint32_t a_addr[2], b_addr[4];
#pragma unroll
    for (int mt = 0; mt < 2; ++mt) {
        int rowA = wm * 32 + mt * 16 + (lane & 15);
        int col  = (lane >> 4) * 8;
        a_addr[mt] = sA + (uint32_t)(rowA * SMH + col) * 2;
    }
#pragma unroll
    for (int ntp = 0; ntp < 4; ++ntp) {
        int rowB = wn * 64 + ntp * 16 + ((lane >> 4) & 1) * 8 + (lane & 7);
        int col  = ((lane >> 3) & 1) * 8;
        b_addr[ntp] = sB + (uint32_t)(rowB * SMH + col) * 2;
    }

    float d[2][8][4];
#pragma unroll
    for (int mt = 0; mt < 2; ++mt)
#pragma unroll
        for (int nt = 0; nt < 8; ++nt)
#pragma unroll
            for (int j = 0; j < 4; ++j) d[mt][nt][j] = 0.f;

    for (int kt = 0; kt < HWD; kt += KC) {
        load_bf_tile(Ag + kt, HWD, As, t);
        load_bf_tile(Bg + kt, HWD, Bs, t);
        __syncthreads();
#pragma unroll
        for (int kh = 0; kh < 4; ++kh) {
            const uint32_t off = kh * 32;
            uint32_t a[2][4], b[4][4];
#pragma unroll
            for (int mt = 0; mt < 2; ++mt)
                ldsm_x4(a[mt][0], a[mt][1], a[mt][2], a[mt][3], a_addr[mt] + off);
#pragma unroll
            for (int ntp = 0; ntp < 4; ++ntp)
                ldsm_x4(b[ntp][0], b[ntp][1], b[ntp][2], b[ntp][3], b_addr[ntp] + off);
#pragma unroll
            for (int mt = 0; mt < 2; ++mt)
#pragma unroll
                for (int nt = 0; nt < 8; ++nt)
                    mma_bf16(d[mt][nt], a[mt][0], a[mt][1], a[mt][2], a[mt][3],
                             b[nt >> 1][(nt & 1) * 2], b[nt >> 1][(nt & 1) * 2 + 1]);
        }
        __syncthreads();
    }

    float* Fn = f + (size_t)n * CC * HWD;
#pragma unroll
    for (int mt = 0; mt < 2; ++mt) {
        const int row = c0 + wm * 32 + mt * 16 + g;
#pragma unroll
        for (int nt = 0; nt < 8; ++nt) {
            const int lc  = wn * 64 + nt * 8 + 2 * tq;
            const int col = p0 + lc;
            float r0 = rinv[lc], r1 = rinv[lc + 1];
            *(float2*)(Fn + (size_t)row * HWD + col) =
                make_float2(d[mt][nt][0] * r0, d[mt][nt][1] * r1);
            *(float2*)(Fn + (size_t)(row + 8) * HWD + col) =
                make_float2(d[mt][nt][2] * r0, d[mt][nt][3] * r1);
        }
    }
}

// ---------------------------------------------------------------------------
// 1x1 conv GEMM (SIMT fp32), standard-layout fp32 output (+ optional residual).
// ---------------------------------------------------------------------------
__global__ __launch_bounds__(256, 2)
void conv_gemm_kernel(const float* __restrict__ W,
                      const float* __restrict__ bias,
                      const float* __restrict__ X,
                      const float* __restrict__ resid,
                      float* __restrict__ out)
{
    __shared__ float Ws[16][132];
    __shared__ float Xs[16][128];

    const int t  = threadIdx.x;
    const int tx = t & 15;
    const int ty = t >> 4;
    const int p0 = blockIdx.x * 128;
    const int o0 = blockIdx.y * 128;
    const int n  = blockIdx.z;

    const float* Xn = X + (size_t)n * CC * HWD;

    float acc[2][2][4][4];
#pragma unroll
    for (int a = 0; a < 2; ++a)
#pragma unroll
        for (int b = 0; b < 2; ++b)
#pragma unroll
            for (int i = 0; i < 4; ++i)
#pragma unroll
                for (int j = 0; j < 4; ++j) acc[a][b][i][j] = 0.f;

    for (int kt = 0; kt < CC; kt += 16) {
#pragma unroll
        for (int i = 0; i < 2; ++i) {
            int v  = t + i * 256;
            int r  = v >> 2;
            int kk = (v & 3) << 2;
            float4 w4 = *(const float4*)(W + (size_t)(o0 + r) * CC + kt + kk);
            Ws[kk + 0][r] = w4.x; Ws[kk + 1][r] = w4.y;
            Ws[kk + 2][r] = w4.z; Ws[kk + 3][r] = w4.w;
        }
#pragma unroll
        for (int i = 0; i < 2; ++i) {
            int v  = t + i * 256;
            int k  = v >> 5;
            int p4 = (v & 31) << 2;
            *(float4*)&Xs[k][p4] =
                *(const float4*)(Xn + (size_t)(kt + k) * HWD + p0 + p4);
        }
        __syncthreads();
#pragma unroll
        for (int k = 0; k < 16; ++k) {
            float a[2][4], b[2][4];
            *(float4*)a[0] = *(const float4*)&Ws[k][ty * 4];
            *(float4*)a[1] = *(const float4*)&Ws[k][64 + ty * 4];
            *(float4*)b[0] = *(const float4*)&Xs[k][tx * 4];
            *(float4*)b[1] = *(const float4*)&Xs[k][64 + tx * 4];
#pragma unroll
            for (int ih = 0; ih < 2; ++ih)
#pragma unroll
                for (int jh = 0; jh < 2; ++jh)
#pragma unroll
                    for (int i = 0; i < 4; ++i)
#pragma unroll
                        for (int j = 0; j < 4; ++j)
                            acc[ih][jh][i][j] += a[ih][i] * b[jh][j];
        }
        __syncthreads();
    }

#pragma unroll
    for (int ih = 0; ih < 2; ++ih) {
#pragma unroll
        for (int i = 0; i < 4; ++i) {
            const int row = o0 + ih * 64 + ty * 4 + i;
            const float bv = bias[row];
#pragma unroll
            for (int jh = 0; jh < 2; ++jh) {
                const int col = p0 + jh * 64 + tx * 4;
                float4 v;
                v.x = acc[ih][jh][i][0] + bv;
                v.y = acc[ih][jh][i][1] + bv;
                v.z = acc[ih][jh][i][2] + bv;
                v.w = acc[ih][jh][i][3] + bv;
                const size_t off = (size_t)n * CC * HWD + (size_t)row * HWD + col;
                if (resid) {
                    float4 rr = *(const float4*)(resid + off);
                    v.x += rr.x; v.y += rr.y; v.z += rr.z; v.w += rr.w;
                }
                *(float4*)(out + off) = v;
            }
        }
    }
}

// ---------------------------------------------------------------------------
// 1x1 conv GEMM with TRANSPOSED bf16 output: outT[n][p][o] (channel-contig),
// feeding the tensor-core scores kernel directly in bf16.
// ---------------------------------------------------------------------------
__global__ __launch_bounds__(256, 2)
void conv_gemm_t_kernel(const float* __restrict__ W,
                        const float* __restrict__ bias,
                        const float* __restrict__ X,
                        __nv_bfloat16* __restrict__ outT)
{
    __shared__ float Ws[16][132];
    __shared__ float Xs[16][128];

    const int t  = threadIdx.x;
    const int tx = t & 15;
    const int ty = t >> 4;
    const int p0 = blockIdx.x * 128;
    const int o0 = blockIdx.y * 128;
    const int n  = blockIdx.z;

    const float* Xn = X + (size_t)n * CC * HWD;

    float acc[2][2][4][4];
#pragma unroll
    for (int a = 0; a < 2; ++a)
#pragma unroll
        for (int b = 0; b < 2; ++b)
#pragma unroll
            for (int i = 0; i < 4; ++i)
#pragma unroll
                for (int j = 0; j < 4; ++j) acc[a][b][i][j] = 0.f;

    for (int kt = 0; kt < CC; kt += 16) {
#pragma unroll
        for (int i = 0; i < 2; ++i) {
            int v  = t + i * 256;
            int r  = v >> 2;
            int kk = (v & 3) << 2;
            float4 w4 = *(const float4*)(W + (size_t)(o0 + r) * CC + kt + kk);
            Ws[kk + 0][r] = w4.x; Ws[kk + 1][r] = w4.y;
            Ws[kk + 2][r] = w4.z; Ws[kk + 3][r] = w4.w;
        }
#pragma unroll
        for (int i = 0; i < 2; ++i) {
            int v  = t + i * 256;
            int k  = v >> 5;
            int p4 = (v & 31) << 2;
            *(float4*)&Xs[k][p4] =
                *(const float4*)(Xn + (size_t)(kt + k) * HWD + p0 + p4);
        }
        __syncthreads();
#pragma unroll
        for (int k = 0; k < 16; ++k) {
            float a[2][4], b[2][4];
            *(float4*)a[0] = *(const float4*)&Ws[k][ty * 4];
            *(float4*)a[1] = *(const float4*)&Ws[k][64 + ty * 4];
            *(float4*)b[0] = *(const float4*)&Xs[k][tx * 4];
            *(float4*)b[1] = *(const float4*)&Xs[k][64 + tx * 4];
#pragma unroll
            for (int ih = 0; ih < 2; ++ih)
#pragma unroll
                for (int jh = 0; jh < 2; ++jh)
#pragma unroll
                    for (int i = 0; i < 4; ++i)
#pragma unroll
                        for (int j = 0; j < 4; ++j)
                            acc[ih][jh][i][j] += a[ih][i] * b[jh][j];
        }
        __syncthreads();
    }

    float bv[2][4];
#pragma unroll
    for (int ih = 0; ih < 2; ++ih)
#pragma unroll
        for (int i = 0; i < 4; ++i) bv[ih][i] = bias[o0 + ih * 64 + ty * 4 + i];

    __nv_bfloat16* On = outT + (size_t)n * HWD * CC;
#pragma unroll
    for (int jh = 0; jh < 2; ++jh) {
#pragma unroll
        for (int j = 0; j < 4; ++j) {
            const int p = p0 + jh * 64 + tx * 4 + j;
#pragma unroll
            for (int ih = 0; ih < 2; ++ih) {
                const int ob = o0 + ih * 64 + ty * 4;
                uint2 v;
                v.x = f22bf(acc[ih][jh][0][j] + bv[ih][0],
                            acc[ih][jh][1][j] + bv[ih][1]);
                v.y = f22bf(acc[ih][jh][2][j] + bv[ih][2],
                            acc[ih][jh][3][j] + bv[ih][3]);
                *(uint2*)(On + (size_t)p * CC + ob) = v;
            }
        }
    }
}

// ---------------------------------------------------------------------------
// Launch
// ---------------------------------------------------------------------------
extern "C" void kernel_launch(void* const* d_in, const int* in_sizes, int n_in,
                              void* d_out, int out_size)
{
    (void)in_sizes; (void)n_in; (void)out_size;
    const float* x       = (const float*)d_in[0];
    const float* theta_w = (const float*)d_in[1];
    const float* theta_b = (const float*)d_in[2];
    const float* phi_w   = (const float*)d_in[3];
    const float* phi_b   = (const float*)d_in[4];
    const float* conv1_w = (const float*)d_in[5];
    const float* conv1_b = (const float*)d_in[6];
    float* out = (float*)d_out;

    __nv_bfloat16 *thT_p, *phT_p, *xbf_p, *expS_p;
    float *rsum_p, *f_p;
    cudaGetSymbolAddress((void**)&thT_p,  g_thetaT);
    cudaGetSymbolAddress((void**)&phT_p,  g_phiT);
    cudaGetSymbolAddress((void**)&xbf_p,  g_xbf);
    cudaGetSymbolAddress((void**)&expS_p, g_expS);
    cudaGetSymbolAddress((void**)&rsum_p, g_rowsum);
    cudaGetSymbolAddress((void**)&f_p,    g_f);

    dim3 blk(256);
    dim3 grid_conv(HWD / 128, CC / 128, NB);   // (32, 2, 4)
    dim3 grid_s(HWD / 128, HWD / 128, NB);     // (32, 32, 4)
    dim3 grid_pv(HWD / 128, CC / 128, NB);     // (32, 2, 4)

    zero_rowsum_kernel<<<NB * HWD / 256, blk>>>(rsum_p);
    cvt_x_kernel<<<(int)((size_t)NB * CC * HWD / (256 * 8)), blk>>>(x, xbf_p);
    conv_gemm_t_kernel<<<grid_conv, blk>>>(theta_w, theta_b, x, thT_p);
    conv_gemm_t_kernel<<<grid_conv, blk>>>(phi_w,   phi_b,   x, phT_p);
    scores_mma_kernel<<<grid_s, blk>>>(thT_p, phT_p, expS_p, rsum_p);
    pv_mma_kernel<<<grid_pv, blk>>>(xbf_p, expS_p, rsum_p, f_p);
    conv_gemm_kernel<<<grid_conv, blk>>>(conv1_w, conv1_b, f_p, x, out);
}

// round 13
// speedup vs baseline: 1.6940x; 1.6940x over previous
#include <cuda_runtime.h>
#include <cuda_bf16.h>
#include <cstdint>
#include <cstddef>

// Problem constants
#define NB  4
#define CC  256
#define HWD 4096

// ---------------------------------------------------------------------------
// Static device scratch (no allocation allowed)
// ---------------------------------------------------------------------------
__device__ __nv_bfloat16 g_theta[(size_t)NB * CC * HWD];  // 8 MB, [n][c][p]
__device__ __nv_bfloat16 g_phi[(size_t)NB * CC * HWD];    // 8 MB, [n][c][q]
__device__ float g_expS[(size_t)NB * HWD * HWD];          // 256 MB, [n][p][q]
__device__ float g_rowsum[NB * HWD];                      // 64 KB
__device__ float g_f[(size_t)NB * CC * HWD];              // 16 MB, [n][c][p]

// ---------------------------------------------------------------------------
// Helpers (all sm_75/80-baseline PTX — no 'a'-suffix features)
// ---------------------------------------------------------------------------
__device__ __forceinline__ uint32_t smem_u32(const void* p) {
    uint32_t a;
    asm("{ .reg .u64 t; cvta.to.shared.u64 t, %1; cvt.u32.u64 %0, t; }"
        : "=r"(a) : "l"(p));
    return a;
}

__device__ __forceinline__ uint32_t f22bf(float x, float y) {
    __nv_bfloat162 h = __floats2bfloat162_rn(x, y);   // low = x
    return *reinterpret_cast<uint32_t*>(&h);
}

__device__ __forceinline__ void ldsm_x4(uint32_t& r0, uint32_t& r1,
                                        uint32_t& r2, uint32_t& r3,
                                        uint32_t addr)
{
    asm volatile("ldmatrix.sync.aligned.m8n8.x4.shared.b16 {%0,%1,%2,%3}, [%4];"
                 : "=r"(r0), "=r"(r1), "=r"(r2), "=r"(r3) : "r"(addr));
}

__device__ __forceinline__ void ldsm_x4_t(uint32_t& r0, uint32_t& r1,
                                          uint32_t& r2, uint32_t& r3,
                                          uint32_t addr)
{
    asm volatile("ldmatrix.sync.aligned.m8n8.x4.trans.shared.b16 {%0,%1,%2,%3}, [%4];"
                 : "=r"(r0), "=r"(r1), "=r"(r2), "=r"(r3) : "r"(addr));
}

__device__ __forceinline__ void mma_bf16(float d[4],
                                         uint32_t a0, uint32_t a1,
                                         uint32_t a2, uint32_t a3,
                                         uint32_t b0, uint32_t b1)
{
    asm volatile(
        "mma.sync.aligned.m16n8k16.row.col.f32.bf16.bf16.f32 "
        "{%0,%1,%2,%3}, {%4,%5,%6,%7}, {%8,%9}, {%0,%1,%2,%3};\n"
        : "+f"(d[0]), "+f"(d[1]), "+f"(d[2]), "+f"(d[3])
        : "r"(a0), "r"(a1), "r"(a2), "r"(a3), "r"(b0), "r"(b1));
}

#define SMH  40   // [row][k] tile stride in halfs (80 B)  — non-trans path
#define SMT  136  // [k][col] tile stride in halfs (272 B) — trans path

// ---------------------------------------------------------------------------
// rowsum zero-init
// ---------------------------------------------------------------------------
__global__ void zero_rowsum_kernel(float* __restrict__ rowsum)
{
    rowsum[blockIdx.x * 256 + threadIdx.x] = 0.f;
}

// ---------------------------------------------------------------------------
// 1x1 conv via bf16 MMA.  out[n,o,p] = sum_k W[o,k]*X[n,k,p] + b[o]
// A = W [o][k] (k-contig, non-trans ldmatrix), B = X [k][p] (p-contig,
// TRANS ldmatrix). Block tile 128(o) x 128(p), K = 256 in chunks of 32.
// Output: either bf16 natural [o][p] (outB) or fp32 + residual (outF).
// ---------------------------------------------------------------------------
__global__ __launch_bounds__(256, 2)
void conv_mma_kernel(const float* __restrict__ W,
                     const float* __restrict__ bias,
                     const float* __restrict__ X,
                     const float* __restrict__ resid,      // may be null
                     float* __restrict__ outF,             // fp32 out (or null)
                     __nv_bfloat16* __restrict__ outB)     // bf16 out (or null)
{
    __shared__ __align__(16) uint16_t As[128 * SMH];   // [o][k]
    __shared__ __align__(16) uint16_t Bs[32 * SMT];    // [k][p]

    const int t    = threadIdx.x;
    const int lane = t & 31;
    const int wid  = t >> 5;
    const int g    = lane >> 2;
    const int tq   = lane & 3;
    const int wm   = wid & 3;
    const int wn   = wid >> 2;

    const int p0 = blockIdx.x * 128;
    const int o0 = blockIdx.y * 128;
    const int n  = blockIdx.z;

    const float* Xn = X + (size_t)n * CC * HWD;

    const uint32_t sA = smem_u32(As), sB = smem_u32(Bs);
    // A fragment (non-trans): rows o, cols k
    uint32_t a_addr[2];
#pragma unroll
    for (int mt = 0; mt < 2; ++mt) {
        int rowA = wm * 32 + mt * 16 + (lane & 15);
        int col  = (lane >> 4) * 8;
        a_addr[mt] = sA + (uint32_t)(rowA * SMH + col) * 2;
    }
    // B fragment (trans): k = (lane&7) + ((lane>>3)&1)*8 ; n_off = (lane>>4)*8
    uint32_t b_addr[4];
    {
        int krow = (lane & 7) + ((lane >> 3) & 1) * 8;
        int noff = (lane >> 4) * 8;
#pragma unroll
        for (int ntp = 0; ntp < 4; ++ntp)
            b_addr[ntp] = sB + (uint32_t)(krow * SMT + wn * 64 + ntp * 16 + noff) * 2;
    }

    float d[2][8][4];
#pragma unroll
    for (int mt = 0; mt < 2; ++mt)
#pragma unroll
        for (int nt = 0; nt < 8; ++nt)
#pragma unroll
            for (int j = 0; j < 4; ++j) d[mt][nt][j] = 0.f;

    for (int kt = 0; kt < CC; kt += 32) {
        // A tile: W[o0..o0+127][kt..kt+31] fp32 -> bf16 (8 f4-chunks/row)
#pragma unroll
        for (int i = 0; i < 4; ++i) {
            int v  = t + i * 256;
            int r  = v >> 3;
            int c4 = (v & 7) * 4;
            float4 w4 = *(const float4*)(W + (size_t)(o0 + r) * CC + kt + c4);
            uint2 h;
            h.x = f22bf(w4.x, w4.y);
            h.y = f22bf(w4.z, w4.w);
            *(uint2*)(As + r * SMH + c4) = h;
        }
        // B tile: X[kt..kt+31][p0..p0+127] fp32 -> bf16 (32 f4-chunks/row)
#pragma unroll
        for (int i = 0; i < 4; ++i) {
            int v  = t + i * 256;
            int r  = v >> 5;
            int c4 = (v & 31) * 4;
            float4 x4 = *(const float4*)(Xn + (size_t)(kt + r) * HWD + p0 + c4);
            uint2 h;
            h.x = f22bf(x4.x, x4.y);
            h.y = f22bf(x4.z, x4.w);
            *(uint2*)(Bs + r * SMT + c4) = h;
        }
        __syncthreads();
#pragma unroll
        for (int kh = 0; kh < 2; ++kh) {
            const uint32_t aoff = kh * 32;              // +16 k cols (32 B)
            const uint32_t boff = kh * 16 * SMT * 2;    // +16 k rows
            uint32_t a[2][4], b[4][4];
#pragma unroll
            for (int mt = 0; mt < 2; ++mt)
                ldsm_x4(a[mt][0], a[mt][1], a[mt][2], a[mt][3], a_addr[mt] + aoff);
#pragma unroll
            for (int ntp = 0; ntp < 4; ++ntp)
                ldsm_x4_t(b[ntp][0], b[ntp][1], b[ntp][2], b[ntp][3], b_addr[ntp] + boff);
#pragma unroll
            for (int mt = 0; mt < 2; ++mt)
#pragma unroll
                for (int nt = 0; nt < 8; ++nt)
                    mma_bf16(d[mt][nt], a[mt][0], a[mt][1], a[mt][2], a[mt][3],
                             b[nt >> 1][(nt & 1) * 2], b[nt >> 1][(nt & 1) * 2 + 1]);
        }
        __syncthreads();
    }

    // Epilogue
#pragma unroll
    for (int mt = 0; mt < 2; ++mt) {
        const int row = o0 + wm * 32 + mt * 16 + g;
        const float bv0 = bias[row];
        const float bv1 = bias[row + 8];
#pragma unroll
        for (int nt = 0; nt < 8; ++nt) {
            const int col = p0 + wn * 64 + nt * 8 + 2 * tq;
            const size_t off0 = (size_t)n * CC * HWD + (size_t)row * HWD + col;
            const size_t off1 = off0 + (size_t)8 * HWD;
            if (outB) {
                *(uint32_t*)(outB + off0) = f22bf(d[mt][nt][0] + bv0, d[mt][nt][1] + bv0);
                *(uint32_t*)(outB + off1) = f22bf(d[mt][nt][2] + bv1, d[mt][nt][3] + bv1);
            } else {
                float2 v0 = make_float2(d[mt][nt][0] + bv0, d[mt][nt][1] + bv0);
                float2 v1 = make_float2(d[mt][nt][2] + bv1, d[mt][nt][3] + bv1);
                if (resid) {
                    float2 r0 = *(const float2*)(resid + off0);
                    float2 r1 = *(const float2*)(resid + off1);
                    v0.x += r0.x; v0.y += r0.y;
                    v1.x += r1.x; v1.y += r1.y;
                }
                *(float2*)(outF + off0) = v0;
                *(float2*)(outF + off1) = v1;
            }
        }
    }
}

// ---------------------------------------------------------------------------
// Scores (bf16 MMA): expS[n,p,q] = exp( (sum_c th[c,p]*ph[c,q]) / 16 )
// A = theta [c][p] natural bf16 (TRANS ldmatrix), B = phi [c][q] (TRANS).
// Block tile 128(p) x 128(q), K = C = 256 in chunks of 32.
// fp32 expS out; rowsums via quad-shfl + atomicAdd (R9-validated epilogue).
// ---------------------------------------------------------------------------
__global__ __launch_bounds__(256, 2)
void scores_mma_kernel(const __nv_bfloat16* __restrict__ th,
                       const __nv_bfloat16* __restrict__ ph,
                       float* __restrict__ expS,
                       float* __restrict__ rowsum)
{
    __shared__ __align__(16) uint16_t As[32 * SMT];   // [c][p]
    __shared__ __align__(16) uint16_t Bs[32 * SMT];   // [c][q]

    const int t    = threadIdx.x;
    const int lane = t & 31;
    const int wid  = t >> 5;
    const int g    = lane >> 2;
    const int tq   = lane & 3;
    const int wm   = wid & 3;
    const int wn   = wid >> 2;

    const int q0 = blockIdx.x * 128;
    const int p0 = blockIdx.y * 128;
    const int n  = blockIdx.z;

    const __nv_bfloat16* Ag = th + (size_t)n * CC * HWD;
    const __nv_bfloat16* Bg = ph + (size_t)n * CC * HWD;

    const uint32_t sA = smem_u32(As), sB = smem_u32(Bs);
    // A trans fragment: k = (lane&7) + (lane>>4)*8 ; m_off = ((lane>>3)&1)*8
    uint32_t a_addr[2];
    {
        int krow = (lane & 7) + (lane >> 4) * 8;
        int moff = ((lane >> 3) & 1) * 8;
#pragma unroll
        for (int mt = 0; mt < 2; ++mt)
            a_addr[mt] = sA + (uint32_t)(krow * SMT + wm * 32 + mt * 16 + moff) * 2;
    }
    // B trans fragment: k = (lane&7) + ((lane>>3)&1)*8 ; n_off = (lane>>4)*8
    uint32_t b_addr[4];
    {
        int krow = (lane & 7) + ((lane >> 3) & 1) * 8;
        int noff = (lane >> 4) * 8;
#pragma unroll
        for (int ntp = 0; ntp < 4; ++ntp)
            b_addr[ntp] = sB + (uint32_t)(krow * SMT + wn * 64 + ntp * 16 + noff) * 2;
    }

    float d[2][8][4];
#pragma unroll
    for (int mt = 0; mt < 2; ++mt)
#pragma unroll
        for (int nt = 0; nt < 8; ++nt)
#pragma unroll
            for (int j = 0; j < 4; ++j) d[mt][nt][j] = 0.f;

    for (int kt = 0; kt < CC; kt += 32) {
        // tiles: 32 c-rows x 128 halfs (16 uint4/row), 2 chunks per thread each
#pragma unroll
        for (int i = 0; i < 2; ++i) {
            int v  = t + i * 256;
            int r  = v >> 4;
            int c8 = (v & 15) * 8;
            *(uint4*)(As + r * SMT + c8) =
                *(const uint4*)(Ag + (size_t)(kt + r) * HWD + p0 + c8);
            *(uint4*)(Bs + r * SMT + c8) =
                *(const uint4*)(Bg + (size_t)(kt + r) * HWD + q0 + c8);
        }
        __syncthreads();
#pragma unroll
        for (int kh = 0; kh < 2; ++kh) {
            const uint32_t off = kh * 16 * SMT * 2;   // +16 k rows
            uint32_t a[2][4], b[4][4];
#pragma unroll
            for (int mt = 0; mt < 2; ++mt)
                ldsm_x4_t(a[mt][0], a[mt][1], a[mt][2], a[mt][3], a_addr[mt] + off);
#pragma unroll
            for (int ntp = 0; ntp < 4; ++ntp)
                ldsm_x4_t(b[ntp][0], b[ntp][1], b[ntp][2], b[ntp][3], b_addr[ntp] + off);
#pragma unroll
            for (int mt = 0; mt < 2; ++mt)
#pragma unroll
                for (int nt = 0; nt < 8; ++nt)
                    mma_bf16(d[mt][nt], a[mt][0], a[mt][1], a[mt][2], a[mt][3],
                             b[nt >> 1][(nt & 1) * 2], b[nt >> 1][(nt & 1) * 2 + 1]);
        }
        __syncthreads();
    }

    // Epilogue: exp, fp32 store, row sums (R9-validated)
    float* Sn = expS + (size_t)n * HWD * HWD;
    float rs[2][2] = {{0.f, 0.f}, {0.f, 0.f}};
#pragma unroll
    for (int mt = 0; mt < 2; ++mt) {
        const int row = p0 + wm * 32 + mt * 16 + g;
#pragma unroll
        for (int nt = 0; nt < 8; ++nt) {
            const int col = q0 + wn * 64 + nt * 8 + 2 * tq;
            float e0 = __expf(d[mt][nt][0] * 0.0625f);
            float e1 = __expf(d[mt][nt][1] * 0.0625f);
            float e2 = __expf(d[mt][nt][2] * 0.0625f);
            float e3 = __expf(d[mt][nt][3] * 0.0625f);
            *(float2*)(Sn + (size_t)row * HWD + col)       = make_float2(e0, e1);
            *(float2*)(Sn + (size_t)(row + 8) * HWD + col) = make_float2(e2, e3);
            rs[mt][0] += e0 + e1;
            rs[mt][1] += e2 + e3;
        }
    }
#pragma unroll
    for (int mt = 0; mt < 2; ++mt)
#pragma unroll
        for (int hh = 0; hh < 2; ++hh) {
            float v = rs[mt][hh];
            v += __shfl_xor_sync(0xFFFFFFFF, v, 1);
            v += __shfl_xor_sync(0xFFFFFFFF, v, 2);
            if (tq == 0)
                atomicAdd(&rowsum[n * HWD + p0 + wm * 32 + mt * 16 + g + hh * 8], v);
        }
}

// ---------------------------------------------------------------------------
// PV (bf16 MMA): f[n,c,p] = (sum_q x[c,q]*expS[p,q]) / rowsum[p]
// EXACT R9 kernel (fp32 inputs, convert-on-load, SMH=40, KC=32).
// ---------------------------------------------------------------------------
__global__ __launch_bounds__(256, 2)
void pv_mma_kernel(const float* __restrict__ x,
                   const float* __restrict__ expS,
                   const float* __restrict__ rowsum,
                   float* __restrict__ f)
{
    __shared__ __align__(16) uint16_t As[128 * SMH];
    __shared__ __align__(16) uint16_t Bs[128 * SMH];
    __shared__ float rinv[128];

    const int t    = threadIdx.x;
    const int lane = t & 31;
    const int wid  = t >> 5;
    const int g    = lane >> 2;
    const int tq   = lane & 3;
    const int wm   = wid & 3;
    const int wn   = wid >> 2;

    const int p0 = blockIdx.x * 128;
    const int c0 = blockIdx.y * 128;
    const int n  = blockIdx.z;

    if (t < 128) rinv[t] = 1.0f / rowsum[n * HWD + p0 + t];

    const float* Ag = x    + (size_t)n * CC * HWD + (size_t)c0 * HWD;
    const float* Bg = expS + (size_t)n * HWD * HWD + (size_t)p0 * HWD;

    const uint32_t sA = smem_u32(As), sB = smem_u32(Bs);
    uint32_t a_addr[2], b_addr[4];
#pragma unroll
    for (int mt = 0; mt < 2; ++mt) {
        int rowA = wm * 32 + mt * 16 + (lane & 15);
        int col  = (lane >> 4) * 8;
        a_addr[mt] = sA + (uint32_t)(rowA * SMH + col) * 2;
    }
#pragma unroll
    for (int ntp = 0; ntp < 4; ++ntp) {
        int rowB = wn * 64 + ntp * 16 + ((lane >> 4) & 1) * 8 + (lane & 7);
        int col  = ((lane >> 3) & 1) * 8;
        b_addr[ntp] = sB + (uint32_t)(rowB * SMH + col) * 2;
    }

    float d[2][8][4];
#pragma unroll
    for (int mt = 0; mt < 2; ++mt)
#pragma unroll
        for (int nt = 0; nt < 8; ++nt)
#pragma unroll
            for (int j = 0; j < 4; ++j) d[mt][nt][j] = 0.f;

    for (int kt = 0; kt < HWD; kt += 32) {
#pragma unroll
        for (int i = 0; i < 4; ++i) {
            int v  = t + i * 256;
            int r  = v >> 3;
            int kq = (v & 7) << 2;
            float4 a4 = *(const float4*)(Ag + (size_t)r * HWD + kt + kq);
            uint32_t* da = (uint32_t*)&As[r * SMH + kq];
            da[0] = f22bf(a4.x, a4.y);
            da[1] = f22bf(a4.z, a4.w);
            float4 b4 = *(const float4*)(Bg + (size_t)r * HWD + kt + kq);
            uint32_t* db = (uint32_t*)&Bs[r * SMH + kq];
            db[0] = f22bf(b4.x, b4.y);
            db[1] = f22bf(b4.z, b4.w);
        }
        __syncthreads();
#pragma unroll
        for (int kh = 0; kh < 2; ++kh) {
            const uint32_t off = kh * 32;
            uint32_t a[2][4], b[4][4];
#pragma unroll
            for (int mt = 0; mt < 2; ++mt)
                ldsm_x4(a[mt][0], a[mt][1], a[mt][2], a[mt][3], a_addr[mt] + off);
#pragma unroll
            for (int ntp = 0; ntp < 4; ++ntp)
                ldsm_x4(b[ntp][0], b[ntp][1], b[ntp][2], b[ntp][3], b_addr[ntp] + off);
#pragma unroll
            for (int mt = 0; mt < 2; ++mt)
#pragma unroll
                for (int nt = 0; nt < 8; ++nt)
                    mma_bf16(d[mt][nt], a[mt][0], a[mt][1], a[mt][2], a[mt][3],
                             b[nt >> 1][(nt & 1) * 2], b[nt >> 1][(nt & 1) * 2 + 1]);
        }
        __syncthreads();
    }

    float* Fn = f + (size_t)n * CC * HWD;
#pragma unroll
    for (int mt = 0; mt < 2; ++mt) {
        const int row = c0 + wm * 32 + mt * 16 + g;
#pragma unroll
        for (int nt = 0; nt < 8; ++nt) {
            const int lc  = wn * 64 + nt * 8 + 2 * tq;
            const int col = p0 + lc;
            float r0 = rinv[lc], r1 = rinv[lc + 1];
            *(float2*)(Fn + (size_t)row * HWD + col) =
                make_float2(d[mt][nt][0] * r0, d[mt][nt][1] * r1);
            *(float2*)(Fn + (size_t)(row + 8) * HWD + col) =
                make_float2(d[mt][nt][2] * r0, d[mt][nt][3] * r1);
        }
    }
}

// ---------------------------------------------------------------------------
// Launch
// ---------------------------------------------------------------------------
extern "C" void kernel_launch(void* const* d_in, const int* in_sizes, int n_in,
                              void* d_out, int out_size)
{
    (void)in_sizes; (void)n_in; (void)out_size;
    const float* x       = (const float*)d_in[0];
    const float* theta_w = (const float*)d_in[1];
    const float* theta_b = (const float*)d_in[2];
    const float* phi_w   = (const float*)d_in[3];
    const float* phi_b   = (const float*)d_in[4];
    const float* conv1_w = (const float*)d_in[5];
    const float* conv1_b = (const float*)d_in[6];
    float* out = (float*)d_out;

    __nv_bfloat16 *th_p, *ph_p;
    float *expS_p, *rsum_p, *f_p;
    cudaGetSymbolAddress((void**)&th_p,   g_theta);
    cudaGetSymbolAddress((void**)&ph_p,   g_phi);
    cudaGetSymbolAddress((void**)&expS_p, g_expS);
    cudaGetSymbolAddress((void**)&rsum_p, g_rowsum);
    cudaGetSymbolAddress((void**)&f_p,    g_f);

    dim3 blk(256);
    dim3 grid_conv(HWD / 128, CC / 128, NB);   // (32, 2, 4)
    dim3 grid_s(HWD / 128, HWD / 128, NB);     // (32, 32, 4)
    dim3 grid_pv(HWD / 128, CC / 128, NB);     // (32, 2, 4)

    zero_rowsum_kernel<<<NB * HWD / 256, blk>>>(rsum_p);
    conv_mma_kernel<<<grid_conv, blk>>>(theta_w, theta_b, x, nullptr, nullptr, th_p);
    conv_mma_kernel<<<grid_conv, blk>>>(phi_w,   phi_b,   x, nullptr, nullptr, ph_p);
    scores_mma_kernel<<<grid_s, blk>>>(th_p, ph_p, expS_p, rsum_p);
    pv_mma_kernel<<<grid_pv, blk>>>(x, expS_p, rsum_p, f_p);
    conv_mma_kernel<<<grid_conv, blk>>>(conv1_w, conv1_b, f_p, x, out, nullptr);
}

// round 17
// speedup vs baseline: 2.1982x; 1.2976x over previous
#include <cuda_runtime.h>
#include <cuda_bf16.h>
#include <cstdint>
#include <cstddef>

// Problem constants
#define NB  4
#define CC  256
#define HWD 4096

// ---------------------------------------------------------------------------
// Static device scratch (no allocation allowed)
// ---------------------------------------------------------------------------
__device__ __nv_bfloat16 g_wbf[3 * CC * CC];              // 384 KB, bf16 weights
__device__ __nv_bfloat16 g_xbf[(size_t)NB * CC * HWD];    // 8 MB, [n][c][p]
__device__ __nv_bfloat16 g_theta[(size_t)NB * CC * HWD];  // 8 MB, [n][c][p]
__device__ __nv_bfloat16 g_phi[(size_t)NB * CC * HWD];    // 8 MB, [n][c][q]
__device__ __nv_bfloat16 g_expS[(size_t)NB * HWD * HWD];  // 128 MB, [n][p][q]
__device__ float g_rowsum[NB * HWD];                      // 64 KB
__device__ __nv_bfloat16 g_fbf[(size_t)NB * CC * HWD];    // 8 MB, [n][c][p]

// ---------------------------------------------------------------------------
// Helpers (all sm_75/80-baseline PTX — no 'a'-suffix features)
// ---------------------------------------------------------------------------
__device__ __forceinline__ uint32_t smem_u32(const void* p) {
    uint32_t a;
    asm("{ .reg .u64 t; cvta.to.shared.u64 t, %1; cvt.u32.u64 %0, t; }"
        : "=r"(a) : "l"(p));
    return a;
}

__device__ __forceinline__ uint32_t f22bf(float x, float y) {
    __nv_bfloat162 h = __floats2bfloat162_rn(x, y);   // low = x
    return *reinterpret_cast<uint32_t*>(&h);
}

__device__ __forceinline__ void cp_async16(uint32_t sdst, const void* gsrc) {
    asm volatile("cp.async.cg.shared.global [%0], [%1], 16;"
                 :: "r"(sdst), "l"(gsrc));
}
#define CP_COMMIT() asm volatile("cp.async.commit_group;" ::: "memory")
#define CP_WAIT1()  asm volatile("cp.async.wait_group 1;" ::: "memory")
#define CP_WAIT0()  asm volatile("cp.async.wait_group 0;" ::: "memory")

__device__ __forceinline__ void ldsm_x4(uint32_t& r0, uint32_t& r1,
                                        uint32_t& r2, uint32_t& r3,
                                        uint32_t addr)
{
    asm volatile("ldmatrix.sync.aligned.m8n8.x4.shared.b16 {%0,%1,%2,%3}, [%4];"
                 : "=r"(r0), "=r"(r1), "=r"(r2), "=r"(r3) : "r"(addr));
}

__device__ __forceinline__ void ldsm_x4_t(uint32_t& r0, uint32_t& r1,
                                          uint32_t& r2, uint32_t& r3,
                                          uint32_t addr)
{
    asm volatile("ldmatrix.sync.aligned.m8n8.x4.trans.shared.b16 {%0,%1,%2,%3}, [%4];"
                 : "=r"(r0), "=r"(r1), "=r"(r2), "=r"(r3) : "r"(addr));
}

__device__ __forceinline__ void mma_bf16(float d[4],
                                         uint32_t a0, uint32_t a1,
                                         uint32_t a2, uint32_t a3,
                                         uint32_t b0, uint32_t b1)
{
    asm volatile(
        "mma.sync.aligned.m16n8k16.row.col.f32.bf16.bf16.f32 "
        "{%0,%1,%2,%3}, {%4,%5,%6,%7}, {%8,%9}, {%0,%1,%2,%3};\n"
        : "+f"(d[0]), "+f"(d[1]), "+f"(d[2]), "+f"(d[3])
        : "r"(a0), "r"(a1), "r"(a2), "r"(a3), "r"(b0), "r"(b1));
}

#define SMH  40        // [row][k] tile stride in halfs (80 B)  — non-trans path
#define SMT  136       // [k][col] tile stride in halfs (272 B) — trans path
#define ST_SMH (128 * SMH)          // 5120 halfs per SMH stage
#define ST_SMT (32 * SMT)           // 4352 halfs per SMT stage
#define STB_SMH (ST_SMH * 2)        // 10240 B
#define STB_SMT (ST_SMT * 2)        // 8704 B

// Tile prefetchers: 128 rows x 32 halfs (SMH) / 32 rows x 128 halfs (SMT).
// g pre-offset to the tile origin; rstride in halfs.
__device__ __forceinline__ void cpa_tile_smh(uint32_t sdst,
                                             const __nv_bfloat16* __restrict__ g,
                                             size_t rstride, int t)
{
#pragma unroll
    for (int i = 0; i < 2; ++i) {
        int v  = t + i * 256;
        int r  = v >> 2;
        int k8 = (v & 3) * 8;
        cp_async16(sdst + (uint32_t)(r * SMH + k8) * 2, g + (size_t)r * rstride + k8);
    }
}
__device__ __forceinline__ void cpa_tile_smt(uint32_t sdst,
                                             const __nv_bfloat16* __restrict__ g,
                                             size_t rstride, int t)
{
#pragma unroll
    for (int i = 0; i < 2; ++i) {
        int v  = t + i * 256;
        int r  = v >> 4;
        int c8 = (v & 15) * 8;
        cp_async16(sdst + (uint32_t)(r * SMT + c8) * 2, g + (size_t)r * rstride + c8);
    }
}

// ---------------------------------------------------------------------------
// Init kernels: zero rowsum; fp32 -> bf16 bulk convert (8 elems/thread)
// ---------------------------------------------------------------------------
__global__ void zero_rowsum_kernel(float* __restrict__ rowsum)
{
    rowsum[blockIdx.x * 256 + threadIdx.x] = 0.f;
}

__global__ void cvt_f32_bf16_kernel(const float* __restrict__ src,
                                    __nv_bfloat16* __restrict__ dst)
{
    size_t i = ((size_t)blockIdx.x * 256 + threadIdx.x) * 8;
    float4 v0 = *(const float4*)(src + i);
    float4 v1 = *(const float4*)(src + i + 4);
    uint4 o;
    o.x = f22bf(v0.x, v0.y);
    o.y = f22bf(v0.z, v0.w);
    o.z = f22bf(v1.x, v1.y);
    o.w = f22bf(v1.z, v1.w);
    *(uint4*)(dst + i) = o;
}

// ---------------------------------------------------------------------------
// 1x1 conv via bf16 MMA, cp.async 2-stage pipeline.
// out[n,o,p] = sum_k W[o,k]*X[n,k,p] + b[o]  (+ optional fp32 residual)
// A = W [o][k] bf16 (non-trans ldsm), B = X [k][p] bf16 (TRANS ldsm).
// ---------------------------------------------------------------------------
__global__ __launch_bounds__(256, 2)
void conv_mma_kernel(const __nv_bfloat16* __restrict__ W,
                     const float* __restrict__ bias,
                     const __nv_bfloat16* __restrict__ X,
                     const float* __restrict__ resid,      // may be null
                     float* __restrict__ outF,             // fp32 out (or null)
                     __nv_bfloat16* __restrict__ outB)     // bf16 out (or null)
{
    __shared__ __align__(16) uint16_t As[2][ST_SMH];   // [o][k]
    __shared__ __align__(16) uint16_t Bs[2][ST_SMT];   // [k][p]

    const int t    = threadIdx.x;
    const int lane = t & 31;
    const int wid  = t >> 5;
    const int g    = lane >> 2;
    const int tq   = lane & 3;
    const int wm   = wid & 3;
    const int wn   = wid >> 2;

    const int p0 = blockIdx.x * 128;
    const int o0 = blockIdx.y * 128;
    const int n  = blockIdx.z;

    const __nv_bfloat16* Wg = W + (size_t)o0 * CC;
    const __nv_bfloat16* Xn = X + (size_t)n * CC * HWD + p0;

    const uint32_t sA = smem_u32(As), sB = smem_u32(Bs);
    uint32_t a_addr[2];
#pragma unroll
    for (int mt = 0; mt < 2; ++mt) {
        int rowA = wm * 32 + mt * 16 + (lane & 15);
        int col  = (lane >> 4) * 8;
        a_addr[mt] = sA + (uint32_t)(rowA * SMH + col) * 2;
    }
    uint32_t b_addr[4];
    {
        int krow = (lane & 7) + ((lane >> 3) & 1) * 8;
        int noff = (lane >> 4) * 8;
#pragma unroll
        for (int ntp = 0; ntp < 4; ++ntp)
            b_addr[ntp] = sB + (uint32_t)(krow * SMT + wn * 64 + ntp * 16 + noff) * 2;
    }

    float d[2][8][4];
#pragma unroll
    for (int mt = 0; mt < 2; ++mt)
#pragma unroll
        for (int nt = 0; nt < 8; ++nt)
#pragma unroll
            for (int j = 0; j < 4; ++j) d[mt][nt][j] = 0.f;

    const int NCH = CC / 32;   // 8
    cpa_tile_smh(sA, Wg, CC, t);
    cpa_tile_smt(sB, Xn, HWD, t);
    CP_COMMIT();

    for (int c = 0; c < NCH; ++c) {
        if (c + 1 < NCH) {
            int s1 = (c + 1) & 1;
            cpa_tile_smh(sA + s1 * STB_SMH, Wg + (c + 1) * 32, CC, t);
            cpa_tile_smt(sB + s1 * STB_SMT, Xn + (size_t)(c + 1) * 32 * HWD, HWD, t);
            CP_COMMIT();
            CP_WAIT1();
        } else {
            CP_WAIT0();
        }
        __syncthreads();
        const uint32_t soA = (uint32_t)(c & 1) * STB_SMH;
        const uint32_t soB = (uint32_t)(c & 1) * STB_SMT;
#pragma unroll
        for (int kh = 0; kh < 2; ++kh) {
            const uint32_t aoff = soA + kh * 32;
            const uint32_t boff = soB + kh * 16 * SMT * 2;
            uint32_t a[2][4], b[4][4];
#pragma unroll
            for (int mt = 0; mt < 2; ++mt)
                ldsm_x4(a[mt][0], a[mt][1], a[mt][2], a[mt][3], a_addr[mt] + aoff);
#pragma unroll
            for (int ntp = 0; ntp < 4; ++ntp)
                ldsm_x4_t(b[ntp][0], b[ntp][1], b[ntp][2], b[ntp][3], b_addr[ntp] + boff);
#pragma unroll
            for (int mt = 0; mt < 2; ++mt)
#pragma unroll
                for (int nt = 0; nt < 8; ++nt)
                    mma_bf16(d[mt][nt], a[mt][0], a[mt][1], a[mt][2], a[mt][3],
                             b[nt >> 1][(nt & 1) * 2], b[nt >> 1][(nt & 1) * 2 + 1]);
        }
        __syncthreads();
    }

    // Epilogue
#pragma unroll
    for (int mt = 0; mt < 2; ++mt) {
        const int row = o0 + wm * 32 + mt * 16 + g;
        const float bv0 = bias[row];
        const float bv1 = bias[row + 8];
#pragma unroll
        for (int nt = 0; nt < 8; ++nt) {
            const int col = p0 + wn * 64 + nt * 8 + 2 * tq;
            const size_t off0 = (size_t)n * CC * HWD + (size_t)row * HWD + col;
            const size_t off1 = off0 + (size_t)8 * HWD;
            if (outB) {
                *(uint32_t*)(outB + off0) = f22bf(d[mt][nt][0] + bv0, d[mt][nt][1] + bv0);
                *(uint32_t*)(outB + off1) = f22bf(d[mt][nt][2] + bv1, d[mt][nt][3] + bv1);
            } else {
                float2 v0 = make_float2(d[mt][nt][0] + bv0, d[mt][nt][1] + bv0);
                float2 v1 = make_float2(d[mt][nt][2] + bv1, d[mt][nt][3] + bv1);
                if (resid) {
                    float2 r0 = *(const float2*)(resid + off0);
                    float2 r1 = *(const float2*)(resid + off1);
                    v0.x += r0.x; v0.y += r0.y;
                    v1.x += r1.x; v1.y += r1.y;
                }
                *(float2*)(outF + off0) = v0;
                *(float2*)(outF + off1) = v1;
            }
        }
    }
}

// ---------------------------------------------------------------------------
// Scores: expS[n,p,q] = bf16( exp( (sum_c th[c,p]*ph[c,q]) / 16 ) )
// Both operands [c][pos] bf16, TRANS ldsm; cp.async 2-stage pipeline.
// Rowsums from the ROUNDED bf16 values (exact softmax normalization).
// ---------------------------------------------------------------------------
__global__ __launch_bounds__(256, 2)
void scores_mma_kernel(const __nv_bfloat16* __restrict__ th,
                       const __nv_bfloat16* __restrict__ ph,
                       __nv_bfloat16* __restrict__ expS,
                       float* __restrict__ rowsum)
{
    __shared__ __align__(16) uint16_t As[2][ST_SMT];   // [c][p]
    __shared__ __align__(16) uint16_t Bs[2][ST_SMT];   // [c][q]

    const int t    = threadIdx.x;
    const int lane = t & 31;
    const int wid  = t >> 5;
    const int g    = lane >> 2;
    const int tq   = lane & 3;
    const int wm   = wid & 3;
    const int wn   = wid >> 2;

    const int q0 = blockIdx.x * 128;
    const int p0 = blockIdx.y * 128;
    const int n  = blockIdx.z;

    const __nv_bfloat16* Ag = th + (size_t)n * CC * HWD + p0;
    const __nv_bfloat16* Bg = ph + (size_t)n * CC * HWD + q0;

    const uint32_t sA = smem_u32(As), sB = smem_u32(Bs);
    uint32_t a_addr[2];
    {
        int krow = (lane & 7) + (lane >> 4) * 8;
        int moff = ((lane >> 3) & 1) * 8;
#pragma unroll
        for (int mt = 0; mt < 2; ++mt)
            a_addr[mt] = sA + (uint32_t)(krow * SMT + wm * 32 + mt * 16 + moff) * 2;
    }
    uint32_t b_addr[4];
    {
        int krow = (lane & 7) + ((lane >> 3) & 1) * 8;
        int noff = (lane >> 4) * 8;
#pragma unroll
        for (int ntp = 0; ntp < 4; ++ntp)
            b_addr[ntp] = sB + (uint32_t)(krow * SMT + wn * 64 + ntp * 16 + noff) * 2;
    }

    float d[2][8][4];
#pragma unroll
    for (int mt = 0; mt < 2; ++mt)
#pragma unroll
        for (int nt = 0; nt < 8; ++nt)
#pragma unroll
            for (int j = 0; j < 4; ++j) d[mt][nt][j] = 0.f;

    const int NCH = CC / 32;   // 8
    cpa_tile_smt(sA, Ag, HWD, t);
    cpa_tile_smt(sB, Bg, HWD, t);
    CP_COMMIT();

    for (int c = 0; c < NCH; ++c) {
        if (c + 1 < NCH) {
            int s1 = (c + 1) & 1;
            cpa_tile_smt(sA + s1 * STB_SMT, Ag + (size_t)(c + 1) * 32 * HWD, HWD, t);
            cpa_tile_smt(sB + s1 * STB_SMT, Bg + (size_t)(c + 1) * 32 * HWD, HWD, t);
            CP_COMMIT();
            CP_WAIT1();
        } else {
            CP_WAIT0();
        }
        __syncthreads();
        const uint32_t so = (uint32_t)(c & 1) * STB_SMT;
#pragma unroll
        for (int kh = 0; kh < 2; ++kh) {
            const uint32_t off = so + kh * 16 * SMT * 2;
            uint32_t a[2][4], b[4][4];
#pragma unroll
            for (int mt = 0; mt < 2; ++mt)
                ldsm_x4_t(a[mt][0], a[mt][1], a[mt][2], a[mt][3], a_addr[mt] + off);
#pragma unroll
            for (int ntp = 0; ntp < 4; ++ntp)
                ldsm_x4_t(b[ntp][0], b[ntp][1], b[ntp][2], b[ntp][3], b_addr[ntp] + off);
#pragma unroll
            for (int mt = 0; mt < 2; ++mt)
#pragma unroll
                for (int nt = 0; nt < 8; ++nt)
                    mma_bf16(d[mt][nt], a[mt][0], a[mt][1], a[mt][2], a[mt][3],
                             b[nt >> 1][(nt & 1) * 2], b[nt >> 1][(nt & 1) * 2 + 1]);
        }
        __syncthreads();
    }

    // Epilogue: exp -> bf16 round -> store; row sums of ROUNDED values
    __nv_bfloat16* Sn = expS + (size_t)n * HWD * HWD;
    float rs[2][2] = {{0.f, 0.f}, {0.f, 0.f}};
#pragma unroll
    for (int mt = 0; mt < 2; ++mt) {
        const int row = p0 + wm * 32 + mt * 16 + g;
#pragma unroll
        for (int nt = 0; nt < 8; ++nt) {
            const int col = q0 + wn * 64 + nt * 8 + 2 * tq;
            float e0 = __expf(d[mt][nt][0] * 0.0625f);
            float e1 = __expf(d[mt][nt][1] * 0.0625f);
            float e2 = __expf(d[mt][nt][2] * 0.0625f);
            float e3 = __expf(d[mt][nt][3] * 0.0625f);
            __nv_bfloat162 lo = __floats2bfloat162_rn(e0, e1);
            __nv_bfloat162 hi = __floats2bfloat162_rn(e2, e3);
            *(uint32_t*)(Sn + (size_t)row * HWD + col)       = *(uint32_t*)&lo;
            *(uint32_t*)(Sn + (size_t)(row + 8) * HWD + col) = *(uint32_t*)&hi;
            rs[mt][0] += __bfloat162float(lo.x) + __bfloat162float(lo.y);
            rs[mt][1] += __bfloat162float(hi.x) + __bfloat162float(hi.y);
        }
    }
#pragma unroll
    for (int mt = 0; mt < 2; ++mt)
#pragma unroll
        for (int hh = 0; hh < 2; ++hh) {
            float v = rs[mt][hh];
            v += __shfl_xor_sync(0xFFFFFFFF, v, 1);
            v += __shfl_xor_sync(0xFFFFFFFF, v, 2);
            if (tq == 0)
                atomicAdd(&rowsum[n * HWD + p0 + wm * 32 + mt * 16 + g + hh * 8], v);
        }
}

// ---------------------------------------------------------------------------
// PV: f[n,c,p] = bf16( (sum_q xbf[c,q]*expS[p,q]) / rowsum[p] )
// Both operands [row][q] bf16 k-contig, non-trans ldsm; cp.async pipeline.
// K = HW = 4096 in 128 chunks of 32.
// ---------------------------------------------------------------------------
__global__ __launch_bounds__(256, 2)
void pv_mma_kernel(const __nv_bfloat16* __restrict__ xbf,
                   const __nv_bfloat16* __restrict__ expS,
                   const float* __restrict__ rowsum,
                   __nv_bfloat16* __restrict__ fbf)
{
    __shared__ __align__(16) uint16_t As[2][ST_SMH];
    __shared__ __align__(16) uint16_t Bs[2][ST_SMH];
    __shared__ float rinv[128];

    const int t    = threadIdx.x;
    const int lane = t & 31;
    const int wid  = t >> 5;
    const int g    = lane >> 2;
    const int tq   = lane & 3;
    const int wm   = wid & 3;
    const int wn   = wid >> 2;

    const int p0 = blockIdx.x * 128;
    const int c0 = blockIdx.y * 128;
    const int n  = blockIdx.z;

    if (t < 128) rinv[t] = 1.0f / rowsum[n * HWD + p0 + t];

    const __nv_bfloat16* Ag = xbf  + (size_t)n * CC * HWD + (size_t)c0 * HWD;
    const __nv_bfloat16* Bg = expS + (size_t)n * HWD * HWD + (size_t)p0 * HWD;

    const uint32_t sA = smem_u32(As), sB = smem_u32(Bs);
    uint32_t a_addr[2], b_addr[4];
#pragma unroll
    for (int mt = 0; mt < 2; ++mt) {
        int rowA = wm * 32 + mt * 16 + (lane & 15);
        int col  = (lane >> 4) * 8;
        a_addr[mt] = sA + (uint32_t)(rowA * SMH + col) * 2;
    }
#pragma unroll
    for (int ntp = 0; ntp < 4; ++ntp) {
        int rowB = wn * 64 + ntp * 16 + ((lane >> 4) & 1) * 8 + (lane & 7);
        int col  = ((lane >> 3) & 1) * 8;
        b_addr[ntp] = sB + (uint32_t)(rowB * SMH + col) * 2;
    }

    float d[2][8][4];
#pragma unroll
    for (int mt = 0; mt < 2; ++mt)
#pragma unroll
        for (int nt = 0; nt < 8; ++nt)
#pragma unroll
            for (int j = 0; j < 4; ++j) d[mt][nt][j] = 0.f;

    const int NCH = HWD / 32;   // 128
    cpa_tile_smh(sA, Ag, HWD, t);
    cpa_tile_smh(sB, Bg, HWD, t);
    CP_COMMIT();

    for (int c = 0; c < NCH; ++c) {
        if (c + 1 < NCH) {
            int s1 = (c + 1) & 1;
            cpa_tile_smh(sA + s1 * STB_SMH, Ag + (c + 1) * 32, HWD, t);
            cpa_tile_smh(sB + s1 * STB_SMH, Bg + (c + 1) * 32, HWD, t);
            CP_COMMIT();
            CP_WAIT1();
        } else {
            CP_WAIT0();
        }
        __syncthreads();
        const uint32_t so = (uint32_t)(c & 1) * STB_SMH;
#pragma unroll
        for (int kh = 0; kh < 2; ++kh) {
            const uint32_t off = so + kh * 32;
            uint32_t a[2][4], b[4][4];
#pragma unroll
            for (int mt = 0; mt < 2; ++mt)
                ldsm_x4(a[mt][0], a[mt][1], a[mt][2], a[mt][3], a_addr[mt] + off);
#pragma unroll
            for (int ntp = 0; ntp < 4; ++ntp)
                ldsm_x4(b[ntp][0], b[ntp][1], b[ntp][2], b[ntp][3], b_addr[ntp] + off);
#pragma unroll
            for (int mt = 0; mt < 2; ++mt)
#pragma unroll
                for (int nt = 0; nt < 8; ++nt)
                    mma_bf16(d[mt][nt], a[mt][0], a[mt][1], a[mt][2], a[mt][3],
                             b[nt >> 1][(nt & 1) * 2], b[nt >> 1][(nt & 1) * 2 + 1]);
        }
        __syncthreads();
    }

    __nv_bfloat16* Fn = fbf + (size_t)n * CC * HWD;
#pragma unroll
    for (int mt = 0; mt < 2; ++mt) {
        const int row = c0 + wm * 32 + mt * 16 + g;
#pragma unroll
        for (int nt = 0; nt < 8; ++nt) {
            const int lc  = wn * 64 + nt * 8 + 2 * tq;
            const int col = p0 + lc;
            float r0 = rinv[lc], r1 = rinv[lc + 1];
            *(uint32_t*)(Fn + (size_t)row * HWD + col) =
                f22bf(d[mt][nt][0] * r0, d[mt][nt][1] * r1);
            *(uint32_t*)(Fn + (size_t)(row + 8) * HWD + col) =
                f22bf(d[mt][nt][2] * r0, d[mt][nt][3] * r1);
        }
    }
}

// ---------------------------------------------------------------------------
// Launch
// ---------------------------------------------------------------------------
extern "C" void kernel_launch(void* const* d_in, const int* in_sizes, int n_in,
                              void* d_out, int out_size)
{
    (void)in_sizes; (void)n_in; (void)out_size;
    const float* x       = (const float*)d_in[0];
    const float* theta_w = (const float*)d_in[1];
    const float* theta_b = (const float*)d_in[2];
    const float* phi_w   = (const float*)d_in[3];
    const float* phi_b   = (const float*)d_in[4];
    const float* conv1_w = (const float*)d_in[5];
    const float* conv1_b = (const float*)d_in[6];
    float* out = (float*)d_out;

    __nv_bfloat16 *wbf_p, *xbf_p, *th_p, *ph_p, *expS_p, *fbf_p;
    float *rsum_p;
    cudaGetSymbolAddress((void**)&wbf_p,  g_wbf);
    cudaGetSymbolAddress((void**)&xbf_p,  g_xbf);
    cudaGetSymbolAddress((void**)&th_p,   g_theta);
    cudaGetSymbolAddress((void**)&ph_p,   g_phi);
    cudaGetSymbolAddress((void**)&expS_p, g_expS);
    cudaGetSymbolAddress((void**)&rsum_p, g_rowsum);
    cudaGetSymbolAddress((void**)&fbf_p,  g_fbf);

    dim3 blk(256);
    dim3 grid_conv(HWD / 128, CC / 128, NB);   // (32, 2, 4)
    dim3 grid_s(HWD / 128, HWD / 128, NB);     // (32, 32, 4)
    dim3 grid_pv(HWD / 128, CC / 128, NB);     // (32, 2, 4)

    const int WELEM = CC * CC;                 // 65536

    zero_rowsum_kernel<<<NB * HWD / 256, blk>>>(rsum_p);
    cvt_f32_bf16_kernel<<<WELEM / (256 * 8), blk>>>(theta_w, wbf_p);
    cvt_f32_bf16_kernel<<<WELEM / (256 * 8), blk>>>(phi_w,   wbf_p + WELEM);
    cvt_f32_bf16_kernel<<<WELEM / (256 * 8), blk>>>(conv1_w, wbf_p + 2 * WELEM);
    cvt_f32_bf16_kernel<<<(int)((size_t)NB * CC * HWD / (256 * 8)), blk>>>(x, xbf_p);

    conv_mma_kernel<<<grid_conv, blk>>>(wbf_p,             theta_b, xbf_p, nullptr, nullptr, th_p);
    conv_mma_kernel<<<grid_conv, blk>>>(wbf_p + WELEM,     phi_b,   xbf_p, nullptr, nullptr, ph_p);
    scores_mma_kernel<<<grid_s, blk>>>(th_p, ph_p, expS_p, rsum_p);
    pv_mma_kernel<<<grid_pv, blk>>>(xbf_p, expS_p, rsum_p, fbf_p);
    conv_mma_kernel<<<grid_conv, blk>>>(wbf_p + 2 * WELEM, conv1_b, fbf_p, x, out, nullptr);
}